// round 1
// baseline (speedup 1.0000x reference)
#include <cuda_runtime.h>

#define NN 50000
#define EE 800000
#define RR 5
#define DD 128

// ---- device scratch (static, allocation-free) ----
__device__ float g_x[NN * DD];                 // 25.6 MB
__device__ float g_y[NN * DD];                 // 25.6 MB
__device__ float g_S[(size_t)NN * RR * DD];    // 128 MB per-(dst,rel) sums
__device__ float g_cnt[NN * RR];               // counts -> inverse counts

__device__ __forceinline__ float lrelu(float v) { return v > 0.f ? v : 0.01f * v; }

__device__ __forceinline__ unsigned long long pack2(float x, float y) {
    unsigned long long r;
    asm("mov.b64 %0, {%1,%2};" : "=l"(r) : "f"(x), "f"(y));
    return r;
}
__device__ __forceinline__ void fma2(unsigned long long& d, unsigned long long a, unsigned long long b) {
    asm("fma.rn.f32x2 %0, %1, %2, %0;" : "+l"(d) : "l"(a), "l"(b));
}
__device__ __forceinline__ float2 unpack2(unsigned long long v) {
    float2 f;
    asm("mov.b64 {%0,%1}, %2;" : "=f"(f.x), "=f"(f.y) : "l"(v));
    return f;
}

// ---- utility kernels ----
__global__ void k_zero(float4* __restrict__ p, int n4) {
    int i = blockIdx.x * blockDim.x + threadIdx.x;
    if (i < n4) p[i] = make_float4(0.f, 0.f, 0.f, 0.f);
}

__global__ void k_count(const int* __restrict__ ei, const int* __restrict__ et,
                        float* __restrict__ cnt) {
    int e = blockIdx.x * blockDim.x + threadIdx.x;
    if (e < EE) atomicAdd(&cnt[ei[EE + e] * RR + et[e]], 1.f);
}

__global__ void k_invert(float* __restrict__ cnt) {
    int i = blockIdx.x * blockDim.x + threadIdx.x;
    if (i < NN * RR) cnt[i] = 1.f / fmaxf(cnt[i], 1.f);
}

// small feature encoders: num_prop [N,6]@[6,32], cat_prop [N,11]@[11,32]
__global__ void k_enc_small(const float* __restrict__ np_, const float* __restrict__ cp,
                            const float* __restrict__ Wnp, const float* __restrict__ bnp,
                            const float* __restrict__ Wcp, const float* __restrict__ bcp,
                            float* __restrict__ q) {
    int i = blockIdx.x * blockDim.x + threadIdx.x;
    if (i >= NN * 64) return;
    int n = i >> 6, c = i & 63;
    float s;
    int col;
    if (c < 32) {
        s = bnp[c];
#pragma unroll
        for (int k = 0; k < 6; k++) s += np_[n * 6 + k] * Wnp[k * 32 + c];
        col = 64 + c;
    } else {
        int cc = c - 32;
        s = bcp[cc];
#pragma unroll
        for (int k = 0; k < 11; k++) s += cp[n * 11 + k] * Wcp[k * 32 + cc];
        col = 96 + cc;
    }
    q[n * DD + col] = lrelu(s);
}

// per-edge scatter: S[dst, r, :] += x[src, :]  (vector red, no return)
__global__ void k_scatter(const float* __restrict__ x, const int* __restrict__ ei,
                          const int* __restrict__ et, float* __restrict__ S) {
    int idx = blockIdx.x * blockDim.x + threadIdx.x;
    if (idx >= EE * 32) return;
    int e = idx >> 5, q = idx & 31;
    int src = ei[e], dst = ei[EE + e], r = et[e];
    float4 v = *reinterpret_cast<const float4*>(&x[src * DD + q * 4]);
    float* p = &S[((size_t)dst * RR + r) * DD + q * 4];
    asm volatile("red.global.add.v4.f32 [%0], {%1,%2,%3,%4};"
                 :: "l"(p), "f"(v.x), "f"(v.y), "f"(v.z), "f"(v.w) : "memory");
}

// ---- tiled GEMM with packed f32x2 FMAs ----
// C[n, col] = sum_k A(n,k) * B(k,col) + bias[col], optional leaky-relu.
// LAYER mode: A(n,k) = k<640 ? S[n,640k]*inv[n, k/128] : x[n, k-640]
//             B rows 0..639 = rel_w (contiguous [5*128,128]), 640..767 = root_w.
template <int BN, int TN, bool ACT, bool LAYER>
__global__ __launch_bounds__(256, 2)
void k_gemm(const float* __restrict__ A, int K,
            const float* __restrict__ B0, const float* __restrict__ B1,
            const float* __restrict__ bias,
            float* __restrict__ C, int ldc,
            const float* __restrict__ Sg, const float* __restrict__ invg) {
    constexpr int BM = 128, BK = 32;
    __shared__ __align__(16) float As[BK][BM + 2];   // pad 2 (even) keeps 8B align + kills bank conflicts
    __shared__ __align__(16) float Bs[BK][BN];

    const int tid = threadIdx.x;
    const int tx = tid & 15, ty = tid >> 4;
    const int n0 = blockIdx.x * BM;

    unsigned long long acc[4][TN];
#pragma unroll
    for (int i = 0; i < 4; i++)
#pragma unroll
        for (int j = 0; j < TN; j++) acc[i][j] = 0ull;

    for (int k0 = 0; k0 < K; k0 += BK) {
        __syncthreads();
        // --- load A tile (128 x 32), stored transposed ---
#pragma unroll
        for (int it = 0; it < 4; it++) {
            int idx = tid + it * 256;
            int row = idx >> 3, kq = idx & 7;
            int grow = n0 + row;
            float4 av = make_float4(0.f, 0.f, 0.f, 0.f);
            if (grow < NN) {
                if (!LAYER) {
                    av = *reinterpret_cast<const float4*>(&A[(size_t)grow * K + k0 + kq * 4]);
                } else if (k0 < 640) {
                    av = *reinterpret_cast<const float4*>(&Sg[(size_t)grow * 640 + k0 + kq * 4]);
                    float sc = invg[grow * RR + (k0 >> 7)];
                    av.x *= sc; av.y *= sc; av.z *= sc; av.w *= sc;
                } else {
                    av = *reinterpret_cast<const float4*>(&A[(size_t)grow * DD + (k0 - 640) + kq * 4]);
                }
            }
            As[kq * 4 + 0][row] = av.x;
            As[kq * 4 + 1][row] = av.y;
            As[kq * 4 + 2][row] = av.z;
            As[kq * 4 + 3][row] = av.w;
        }
        // --- load B tile (32 x BN) ---
        const float* Bp;
        if (!LAYER) Bp = B0 + (size_t)k0 * BN;
        else        Bp = (k0 < 640) ? (B0 + (size_t)k0 * DD) : (B1 + (size_t)(k0 - 640) * DD);
#pragma unroll
        for (int it = 0; it < (BK * BN / 4) / 256; it++) {
            int idx = tid + it * 256;
            int kk = idx / (BN / 4), cq = idx % (BN / 4);
            *reinterpret_cast<float4*>(&Bs[kk][cq * 4]) =
                *reinterpret_cast<const float4*>(&Bp[(size_t)kk * BN + cq * 4]);
        }
        __syncthreads();
        // --- inner product: rows paired into f32x2, B broadcast-packed ---
#pragma unroll 8
        for (int kk = 0; kk < BK; kk++) {
            unsigned long long a2[4];
#pragma unroll
            for (int i = 0; i < 4; i++)
                a2[i] = *reinterpret_cast<const unsigned long long*>(&As[kk][ty * 8 + 2 * i]);
#pragma unroll
            for (int j = 0; j < TN; j++) {
                float b = Bs[kk][tx + 16 * j];
                unsigned long long bp = pack2(b, b);
#pragma unroll
                for (int i = 0; i < 4; i++) fma2(acc[i][j], a2[i], bp);
            }
        }
    }
    // --- epilogue ---
#pragma unroll
    for (int i = 0; i < 4; i++) {
        int grow = n0 + ty * 8 + 2 * i;
#pragma unroll
        for (int j = 0; j < TN; j++) {
            int col = tx + 16 * j;
            float2 r = unpack2(acc[i][j]);
            float c0 = r.x + bias[col];
            float c1 = r.y + bias[col];
            if (ACT) { c0 = lrelu(c0); c1 = lrelu(c1); }
            if (grow < NN)     C[(size_t)grow * ldc + col]       = c0;
            if (grow + 1 < NN) C[(size_t)(grow + 1) * ldc + col] = c1;
        }
    }
}

// output head: out[n, j] = sum_k z[n,k] * W_o2[k,j] + b_o2[j], one warp per node
__global__ void k_head(const float* __restrict__ z, const float* __restrict__ W,
                       const float* __restrict__ b, float* __restrict__ out) {
    int gt = blockIdx.x * blockDim.x + threadIdx.x;
    int warp = gt >> 5, lane = gt & 31;
    if (warp >= NN) return;
    float4 v = *reinterpret_cast<const float4*>(&z[warp * DD + lane * 4]);
    float arr[4] = {v.x, v.y, v.z, v.w};
    float s0 = 0.f, s1 = 0.f;
#pragma unroll
    for (int t = 0; t < 4; t++) {
        s0 += arr[t] * W[(lane * 4 + t) * 2 + 0];
        s1 += arr[t] * W[(lane * 4 + t) * 2 + 1];
    }
#pragma unroll
    for (int o = 16; o > 0; o >>= 1) {
        s0 += __shfl_xor_sync(0xffffffffu, s0, o);
        s1 += __shfl_xor_sync(0xffffffffu, s1, o);
    }
    if (lane == 0) {
        out[warp * 2 + 0] = s0 + b[0];
        out[warp * 2 + 1] = s1 + b[1];
    }
}

extern "C" void kernel_launch(void* const* d_in, const int* in_sizes, int n_in,
                              void* d_out, int out_size) {
    const float* des    = (const float*)d_in[0];
    const float* tweet  = (const float*)d_in[1];
    const float* np_    = (const float*)d_in[2];
    const float* cp     = (const float*)d_in[3];
    const int*   ei     = (const int*)d_in[4];
    const int*   et     = (const int*)d_in[5];
    const float* W_des  = (const float*)d_in[6];
    const float* b_des  = (const float*)d_in[7];
    const float* W_tw   = (const float*)d_in[8];
    const float* b_tw   = (const float*)d_in[9];
    const float* W_np   = (const float*)d_in[10];
    const float* b_np   = (const float*)d_in[11];
    const float* W_cp   = (const float*)d_in[12];
    const float* b_cp   = (const float*)d_in[13];
    const float* W_in   = (const float*)d_in[14];
    const float* b_in   = (const float*)d_in[15];
    const float* rel_w  = (const float*)d_in[16];
    const float* root_w = (const float*)d_in[17];
    const float* rgcn_b = (const float*)d_in[18];
    const float* W_o1   = (const float*)d_in[19];
    const float* b_o1   = (const float*)d_in[20];
    const float* W_o2   = (const float*)d_in[21];
    const float* b_o2   = (const float*)d_in[22];
    float* out = (float*)d_out;

    void *vx, *vy, *vS, *vc;
    cudaGetSymbolAddress(&vx, g_x);
    cudaGetSymbolAddress(&vy, g_y);
    cudaGetSymbolAddress(&vS, g_S);
    cudaGetSymbolAddress(&vc, g_cnt);
    float* px = (float*)vx;
    float* py = (float*)vy;
    float* pS = (float*)vS;
    float* pc = (float*)vc;

    const int GB = (NN + 127) / 128;  // 391 row tiles

    // edge counts -> inverse counts (structure fixed across the 4 layers)
    k_zero<<<(NN * RR / 4 + 255) / 256, 256>>>((float4*)pc, NN * RR / 4);
    k_count<<<(EE + 255) / 256, 256>>>(ei, et, pc);
    k_invert<<<(NN * RR + 255) / 256, 256>>>(pc);

    // feature encode -> q in g_y
    k_gemm<32, 2, true, false><<<GB, 256>>>(des,   768, W_des, nullptr, b_des, py + 0,  DD, nullptr, nullptr);
    k_gemm<32, 2, true, false><<<GB, 256>>>(tweet, 768, W_tw,  nullptr, b_tw,  py + 32, DD, nullptr, nullptr);
    k_enc_small<<<(NN * 64 + 255) / 256, 256>>>(np_, cp, W_np, b_np, W_cp, b_cp, py);

    // x = lrelu(q @ W_in + b_in) -> g_x
    k_gemm<128, 8, true, false><<<GB, 256>>>(py, 128, W_in, nullptr, b_in, px, DD, nullptr, nullptr);

    // 4 shared RGCN layers
    float* cur = px;
    float* nxt = py;
    for (int l = 0; l < 4; l++) {
        k_zero<<<(NN * RR * DD / 4 + 255) / 256, 256>>>((float4*)pS, NN * RR * DD / 4);
        k_scatter<<<(EE * 32 + 255) / 256, 256>>>(cur, ei, et, pS);
        k_gemm<128, 8, false, true><<<GB, 256>>>(cur, 768, rel_w, root_w, rgcn_b, nxt, DD, pS, pc);
        float* t = cur; cur = nxt; nxt = t;
    }

    // head: z = lrelu(x @ W_o1 + b_o1); out = z @ W_o2 + b_o2
    k_gemm<128, 8, true, false><<<GB, 256>>>(cur, 128, W_o1, nullptr, b_o1, nxt, DD, nullptr, nullptr);
    k_head<<<(NN * 32 + 255) / 256, 256>>>(nxt, W_o2, b_o2, out);
}

// round 3
// speedup vs baseline: 1.2255x; 1.2255x over previous
#include <cuda_runtime.h>
#include <cuda_bf16.h>
#include <cstdint>

#define NN 50000
#define EE 800000
#define RR 5
#define DD 128

// ---------------- device scratch ----------------
__device__ float g_x[NN * DD];
__device__ float g_y[NN * DD];
__device__ float g_S[(size_t)NN * RR * DD];
__device__ float g_cnt[NN * RR];

// prepped (transposed, split) B matrices: [Ncols][K] bf16, hi and lo
#define OFF_LAYER 0
#define OFF_DES   (128 * 768)
#define OFF_TW    (OFF_DES + 32 * 768)
#define OFF_IN    (OFF_TW + 32 * 768)
#define OFF_O1    (OFF_IN + 128 * 128)
#define BT_TOTAL  (OFF_O1 + 128 * 128)
__device__ __nv_bfloat16 g_Bh[BT_TOTAL];
__device__ __nv_bfloat16 g_Bl[BT_TOTAL];

__device__ __forceinline__ float lrelu(float v) { return v > 0.f ? v : 0.01f * v; }

__device__ __forceinline__ void mma16816(float* d, const uint32_t* a, const uint32_t* b) {
    asm volatile(
        "mma.sync.aligned.m16n8k16.row.col.f32.bf16.bf16.f32 "
        "{%0,%1,%2,%3}, {%4,%5,%6,%7}, {%8,%9}, {%0,%1,%2,%3};"
        : "+f"(d[0]), "+f"(d[1]), "+f"(d[2]), "+f"(d[3])
        : "r"(a[0]), "r"(a[1]), "r"(a[2]), "r"(a[3]), "r"(b[0]), "r"(b[1]));
}

// ---------------- utility kernels ----------------
__global__ void k_zero(float4* __restrict__ p, int n4) {
    int i = blockIdx.x * blockDim.x + threadIdx.x;
    if (i < n4) p[i] = make_float4(0.f, 0.f, 0.f, 0.f);
}
__global__ void k_count(const int* __restrict__ ei, const int* __restrict__ et, float* __restrict__ cnt) {
    int e = blockIdx.x * blockDim.x + threadIdx.x;
    if (e < EE) atomicAdd(&cnt[ei[EE + e] * RR + et[e]], 1.f);
}
__global__ void k_invert(float* __restrict__ cnt) {
    int i = blockIdx.x * blockDim.x + threadIdx.x;
    if (i < NN * RR) cnt[i] = 1.f / fmaxf(cnt[i], 1.f);
}
// split+transpose B: src row-major [K][Nc] (two segments) -> Bt [Nc][K] hi/lo bf16
__global__ void k_prep(const float* __restrict__ B0, int K0, const float* __restrict__ B1,
                       int K, int Nc, __nv_bfloat16* __restrict__ Bh, __nv_bfloat16* __restrict__ Bl) {
    int i = blockIdx.x * blockDim.x + threadIdx.x;
    if (i >= Nc * K) return;
    int n = i / K, k = i % K;
    float v = (k < K0) ? B0[(size_t)k * Nc + n] : B1[(size_t)(k - K0) * Nc + n];
    __nv_bfloat16 h = __float2bfloat16_rn(v);
    Bh[(size_t)n * K + k] = h;
    Bl[(size_t)n * K + k] = __float2bfloat16_rn(v - __bfloat162float(h));
}
__global__ void k_enc_small(const float* __restrict__ np_, const float* __restrict__ cp,
                            const float* __restrict__ Wnp, const float* __restrict__ bnp,
                            const float* __restrict__ Wcp, const float* __restrict__ bcp,
                            float* __restrict__ q) {
    int i = blockIdx.x * blockDim.x + threadIdx.x;
    if (i >= NN * 64) return;
    int n = i >> 6, c = i & 63;
    float s; int col;
    if (c < 32) {
        s = bnp[c];
#pragma unroll
        for (int k = 0; k < 6; k++) s += np_[n * 6 + k] * Wnp[k * 32 + c];
        col = 64 + c;
    } else {
        int cc = c - 32;
        s = bcp[cc];
#pragma unroll
        for (int k = 0; k < 11; k++) s += cp[n * 11 + k] * Wcp[k * 32 + cc];
        col = 96 + cc;
    }
    q[n * DD + col] = lrelu(s);
}
__global__ void k_scatter(const float* __restrict__ x, const int* __restrict__ ei,
                          const int* __restrict__ et, const float* __restrict__ inv) {
    int idx = blockIdx.x * blockDim.x + threadIdx.x;
    if (idx >= EE * 32) return;
    int e = idx >> 5, q = idx & 31;
    int src = ei[e], dst = ei[EE + e], r = et[e];
    float sc = inv[dst * RR + r];
    float4 v = *reinterpret_cast<const float4*>(&x[src * DD + q * 4]);
    float* p = &g_S[((size_t)dst * RR + r) * DD + q * 4];
    asm volatile("red.global.add.v4.f32 [%0], {%1,%2,%3,%4};"
                 :: "l"(p), "f"(v.x * sc), "f"(v.y * sc), "f"(v.z * sc), "f"(v.w * sc) : "memory");
}
__global__ void k_head(const float* __restrict__ z, const float* __restrict__ W,
                       const float* __restrict__ b, float* __restrict__ out) {
    int gt = blockIdx.x * blockDim.x + threadIdx.x;
    int warp = gt >> 5, lane = gt & 31;
    if (warp >= NN) return;
    float4 v = *reinterpret_cast<const float4*>(&z[warp * DD + lane * 4]);
    float arr[4] = {v.x, v.y, v.z, v.w};
    float s0 = 0.f, s1 = 0.f;
#pragma unroll
    for (int t = 0; t < 4; t++) {
        s0 += arr[t] * W[(lane * 4 + t) * 2 + 0];
        s1 += arr[t] * W[(lane * 4 + t) * 2 + 1];
    }
#pragma unroll
    for (int o = 16; o > 0; o >>= 1) {
        s0 += __shfl_xor_sync(0xffffffffu, s0, o);
        s1 += __shfl_xor_sync(0xffffffffu, s1, o);
    }
    if (lane == 0) { out[warp * 2 + 0] = s0 + b[0]; out[warp * 2 + 1] = s1 + b[1]; }
}

// ---------------- mma.sync split-bf16 GEMM ----------------
// C[128-tile, BN] = A @ Bt^T, A fp32 (k<K0 from A0, else A1), Bt [BN][K] pre-split bf16.
// smem holds tiles in mma fragment order: A word ((mb*2+ks)*32+lane)*4+r ; B ((nb*2+ks)*32+lane)*2+r.
template <int BN, bool ACT>
__global__ __launch_bounds__(256, 1)
void k_mma(const float* __restrict__ A0, int lda0, int K0,
           const float* __restrict__ A1, int lda1,
           const __nv_bfloat16* __restrict__ Bh, const __nv_bfloat16* __restrict__ Bl,
           int K, const float* __restrict__ bias, float* __restrict__ C, int ldc) {
    constexpr int A_WORDS = 2048;                 // per (stage, hi/lo)
    constexpr int B_WORDS = (BN / 8) * 2 * 32 * 2;
    constexpr int MBW = (BN == 128) ? 4 : 1;      // m16-blocks per warp
    constexpr int NBC = (BN == 128) ? 4 : 1;      // B chunks per thread per stage
    extern __shared__ uint32_t sm[];              // A: 4*A_WORDS, B at 8192

    const int tid = threadIdx.x, lane = tid & 31, wid = tid >> 5;
    const int wm = (BN == 128) ? (wid >> 2) : wid;
    const int wn = (BN == 128) ? (wid & 3) : 0;
    const int n0 = blockIdx.x * 128;
    const int NC = K / 32;

    float acc[MBW][4][4];
#pragma unroll
    for (int i = 0; i < MBW; i++)
#pragma unroll
        for (int j = 0; j < 4; j++)
#pragma unroll
            for (int q = 0; q < 4; q++) acc[i][j][q] = 0.f;

    float4 av[4];
    uint4 bv[NBC];

#define GLOAD(I) do { \
    int k0 = (I) * 32; const float* Ap; int lda, kb; \
    if (k0 < K0) { Ap = A0; lda = lda0; kb = k0; } else { Ap = A1; lda = lda1; kb = k0 - K0; } \
    _Pragma("unroll") \
    for (int it = 0; it < 4; it++) { \
        int idx = it * 256 + tid; int row = idx >> 3, c4 = (idx & 7) * 4; int grow = n0 + row; \
        av[it] = make_float4(0.f, 0.f, 0.f, 0.f); \
        if (grow < NN) av[it] = *reinterpret_cast<const float4*>(&Ap[(size_t)grow * lda + kb + c4]); \
    } \
    _Pragma("unroll") \
    for (int it = 0; it < NBC; it++) { \
        int idx = it * 256 + tid; int m = idx >= BN * 4; int idx2 = m ? idx - BN * 4 : idx; \
        int n = idx2 & (BN - 1); int kc = idx2 / BN; \
        const __nv_bfloat16* src = (m ? Bl : Bh) + (size_t)n * K + k0 + kc * 8; \
        bv[it] = *reinterpret_cast<const uint4*>(src); \
    } \
} while (0)

#define SSTORE(I) do { \
    int s_ = (I) & 1; \
    _Pragma("unroll") \
    for (int it = 0; it < 4; it++) { \
        int idx = it * 256 + tid; int row = idx >> 3, c4 = (idx & 7) * 4; \
        int mb = row >> 4, rm = row & 15, g = rm & 7, r1 = rm >> 3; \
        int ks = c4 >> 4, khalf = ((c4 & 15) >= 8) ? 1 : 0, r = r1 + 2 * khalf, t0 = (c4 >> 1) & 3; \
        float4 v = av[it]; \
        __nv_bfloat16 h0 = __float2bfloat16_rn(v.x), h1 = __float2bfloat16_rn(v.y); \
        __nv_bfloat16 h2 = __float2bfloat16_rn(v.z), h3 = __float2bfloat16_rn(v.w); \
        __nv_bfloat162 H01(h0, h1), H23(h2, h3); \
        __nv_bfloat162 L01 = __floats2bfloat162_rn(v.x - __bfloat162float(h0), v.y - __bfloat162float(h1)); \
        __nv_bfloat162 L23 = __floats2bfloat162_rn(v.z - __bfloat162float(h2), v.w - __bfloat162float(h3)); \
        int base = ((mb * 2 + ks) * 32) * 4 + r; \
        int ab0 = (s_ * 2 + 0) * A_WORDS + base, ab1 = (s_ * 2 + 1) * A_WORDS + base; \
        sm[ab0 + (g * 4 + t0) * 4]     = *reinterpret_cast<uint32_t*>(&H01); \
        sm[ab0 + (g * 4 + t0 + 1) * 4] = *reinterpret_cast<uint32_t*>(&H23); \
        sm[ab1 + (g * 4 + t0) * 4]     = *reinterpret_cast<uint32_t*>(&L01); \
        sm[ab1 + (g * 4 + t0 + 1) * 4] = *reinterpret_cast<uint32_t*>(&L23); \
    } \
    _Pragma("unroll") \
    for (int it = 0; it < NBC; it++) { \
        int idx = it * 256 + tid; int m = idx >= BN * 4; int idx2 = m ? idx - BN * 4 : idx; \
        int n = idx2 & (BN - 1); int kc = idx2 / BN; \
        int ks = kc >> 1, r = kc & 1, nb = n >> 3, g = n & 7; \
        int a0 = 8192 + (s_ * 2 + m) * B_WORDS + ((nb * 2 + ks) * 32 + g * 4) * 2 + r; \
        sm[a0 + 0] = bv[it].x; sm[a0 + 2] = bv[it].y; sm[a0 + 4] = bv[it].z; sm[a0 + 6] = bv[it].w; \
    } \
} while (0)

#define COMPUTE(I) do { \
    int s_ = (I) & 1; \
    _Pragma("unroll") \
    for (int ks = 0; ks < 2; ks++) { \
        uint32_t bhF[4][2], blF[4][2]; \
        _Pragma("unroll") \
        for (int nb = 0; nb < 4; nb++) { \
            int nb_g = wn * 4 + nb; \
            uint2 h = *reinterpret_cast<uint2*>(&sm[8192 + (s_ * 2 + 0) * B_WORDS + ((nb_g * 2 + ks) * 32 + lane) * 2]); \
            uint2 l = *reinterpret_cast<uint2*>(&sm[8192 + (s_ * 2 + 1) * B_WORDS + ((nb_g * 2 + ks) * 32 + lane) * 2]); \
            bhF[nb][0] = h.x; bhF[nb][1] = h.y; blF[nb][0] = l.x; blF[nb][1] = l.y; \
        } \
        _Pragma("unroll") \
        for (int mb = 0; mb < MBW; mb++) { \
            int mb_g = wm * MBW + mb; \
            uint4 ah4 = *reinterpret_cast<uint4*>(&sm[(s_ * 2 + 0) * A_WORDS + ((mb_g * 2 + ks) * 32 + lane) * 4]); \
            uint4 al4 = *reinterpret_cast<uint4*>(&sm[(s_ * 2 + 1) * A_WORDS + ((mb_g * 2 + ks) * 32 + lane) * 4]); \
            uint32_t ah[4] = {ah4.x, ah4.y, ah4.z, ah4.w}; \
            uint32_t al[4] = {al4.x, al4.y, al4.z, al4.w}; \
            _Pragma("unroll") \
            for (int nb = 0; nb < 4; nb++) { \
                mma16816(acc[mb][nb], ah, bhF[nb]); \
                mma16816(acc[mb][nb], ah, blF[nb]); \
                mma16816(acc[mb][nb], al, bhF[nb]); \
            } \
        } \
    } \
} while (0)

    GLOAD(0);
    SSTORE(0);
    __syncthreads();
    for (int i = 0; i < NC; i++) {
        if (i + 1 < NC) GLOAD(i + 1);
        COMPUTE(i);
        if (i + 1 < NC) SSTORE(i + 1);
        __syncthreads();
    }

    // epilogue: direct float2 stores
    int g = lane >> 2, t = lane & 3;
#pragma unroll
    for (int mb = 0; mb < MBW; mb++) {
#pragma unroll
        for (int nb = 0; nb < 4; nb++) {
            int col = (wn * 4 + nb) * 8 + 2 * t;
            float b0 = bias[col], b1 = bias[col + 1];
            int row0 = n0 + wm * (MBW * 16) + mb * 16 + g;
            float c0 = acc[mb][nb][0] + b0, c1 = acc[mb][nb][1] + b1;
            float c2 = acc[mb][nb][2] + b0, c3 = acc[mb][nb][3] + b1;
            if (ACT) { c0 = lrelu(c0); c1 = lrelu(c1); c2 = lrelu(c2); c3 = lrelu(c3); }
            if (row0 < NN) *reinterpret_cast<float2*>(&C[(size_t)row0 * ldc + col]) = make_float2(c0, c1);
            if (row0 + 8 < NN) *reinterpret_cast<float2*>(&C[(size_t)(row0 + 8) * ldc + col]) = make_float2(c2, c3);
        }
    }
#undef GLOAD
#undef SSTORE
#undef COMPUTE
}

// ---------------- host launch ----------------
extern "C" void kernel_launch(void* const* d_in, const int* in_sizes, int n_in,
                              void* d_out, int out_size) {
    const float* des = (const float*)d_in[0];
    const float* tweet = (const float*)d_in[1];
    const float* np_ = (const float*)d_in[2];
    const float* cp = (const float*)d_in[3];
    const int* ei = (const int*)d_in[4];
    const int* et = (const int*)d_in[5];
    const float* W_des = (const float*)d_in[6];
    const float* b_des = (const float*)d_in[7];
    const float* W_tw = (const float*)d_in[8];
    const float* b_tw = (const float*)d_in[9];
    const float* W_np = (const float*)d_in[10];
    const float* b_np = (const float*)d_in[11];
    const float* W_cp = (const float*)d_in[12];
    const float* b_cp = (const float*)d_in[13];
    const float* W_in = (const float*)d_in[14];
    const float* b_in = (const float*)d_in[15];
    const float* rel_w = (const float*)d_in[16];
    const float* root_w = (const float*)d_in[17];
    const float* rgcn_b = (const float*)d_in[18];
    const float* W_o1 = (const float*)d_in[19];
    const float* b_o1 = (const float*)d_in[20];
    const float* W_o2 = (const float*)d_in[21];
    const float* b_o2 = (const float*)d_in[22];
    float* out = (float*)d_out;

    void *vx, *vy, *vc, *vbh, *vbl;
    cudaGetSymbolAddress(&vx, g_x);
    cudaGetSymbolAddress(&vy, g_y);
    cudaGetSymbolAddress(&vc, g_cnt);
    cudaGetSymbolAddress(&vbh, g_Bh);
    cudaGetSymbolAddress(&vbl, g_Bl);
    float* px = (float*)vx;
    float* py = (float*)vy;
    float* pc = (float*)vc;
    __nv_bfloat16* pBh = (__nv_bfloat16*)vbh;
    __nv_bfloat16* pBl = (__nv_bfloat16*)vbl;
    void* vS;
    cudaGetSymbolAddress(&vS, g_S);
    float* pS = (float*)vS;

    const int SMEM128 = (8192 + 4 * 2048) * 4;  // 64 KB
    const int SMEM32  = (8192 + 4 * 512) * 4;   // 40 KB
    cudaFuncSetAttribute(k_mma<128, false>, cudaFuncAttributeMaxDynamicSharedMemorySize, SMEM128);
    cudaFuncSetAttribute(k_mma<128, true>,  cudaFuncAttributeMaxDynamicSharedMemorySize, SMEM128);
    cudaFuncSetAttribute(k_mma<32, true>,   cudaFuncAttributeMaxDynamicSharedMemorySize, SMEM32);

    const int GB = (NN + 127) / 128;

    // B preps
    k_prep<<<(128 * 768 + 255) / 256, 256>>>(rel_w, 640, root_w, 768, 128, pBh + OFF_LAYER, pBl + OFF_LAYER);
    k_prep<<<(32 * 768 + 255) / 256, 256>>>(W_des, 768, nullptr, 768, 32, pBh + OFF_DES, pBl + OFF_DES);
    k_prep<<<(32 * 768 + 255) / 256, 256>>>(W_tw, 768, nullptr, 768, 32, pBh + OFF_TW, pBl + OFF_TW);
    k_prep<<<(128 * 128 + 255) / 256, 256>>>(W_in, 128, nullptr, 128, 128, pBh + OFF_IN, pBl + OFF_IN);
    k_prep<<<(128 * 128 + 255) / 256, 256>>>(W_o1, 128, nullptr, 128, 128, pBh + OFF_O1, pBl + OFF_O1);

    // edge counts -> inverse counts
    k_zero<<<(NN * RR / 4 + 255) / 256, 256>>>((float4*)pc, NN * RR / 4);
    k_count<<<(EE + 255) / 256, 256>>>(ei, et, pc);
    k_invert<<<(NN * RR + 255) / 256, 256>>>(pc);

    // feature encoders -> y
    k_mma<32, true><<<GB, 256, SMEM32>>>(des, 768, 768, nullptr, 0, pBh + OFF_DES, pBl + OFF_DES, 768, b_des, py + 0, DD);
    k_mma<32, true><<<GB, 256, SMEM32>>>(tweet, 768, 768, nullptr, 0, pBh + OFF_TW, pBl + OFF_TW, 768, b_tw, py + 32, DD);
    k_enc_small<<<(NN * 64 + 255) / 256, 256>>>(np_, cp, W_np, b_np, W_cp, b_cp, py);

    // x = lrelu(y @ W_in + b_in)
    k_mma<128, true><<<GB, 256, SMEM128>>>(py, 128, 128, nullptr, 0, pBh + OFF_IN, pBl + OFF_IN, 128, b_in, px, DD);

    // 4 shared RGCN layers
    float* cur = px;
    float* nxt = py;
    for (int l = 0; l < 4; l++) {
        k_zero<<<(NN * RR * DD / 4 + 255) / 256, 256>>>((float4*)pS, NN * RR * DD / 4);
        k_scatter<<<(EE * 32 + 255) / 256, 256>>>(cur, ei, et, pc);
        k_mma<128, false><<<GB, 256, SMEM128>>>(pS, 640, 640, cur, 128, pBh + OFF_LAYER, pBl + OFF_LAYER,
                                                768, rgcn_b, nxt, DD);
        float* t = cur; cur = nxt; nxt = t;
    }

    // head
    k_mma<128, true><<<GB, 256, SMEM128>>>(cur, 128, 128, nullptr, 0, pBh + OFF_O1, pBl + OFF_O1, 128, b_o1, nxt, DD);
    k_head<<<(NN * 32 + 255) / 256, 256>>>(nxt, W_o2, b_o2, out);
}

// round 4
// speedup vs baseline: 1.8965x; 1.5475x over previous
#include <cuda_runtime.h>
#include <cuda_bf16.h>
#include <cstdint>

#define NN 50000
#define EE 800000
#define RR 5
#define DD 128
#define NBKT (NN * RR)           // 250000 (dst,rel) buckets
#define SCAN_T 256
#define SCAN_ELT 8
#define SCAN_BLOCK (SCAN_T * SCAN_ELT)            // 2048
#define NSCB ((NBKT + SCAN_BLOCK - 1) / SCAN_BLOCK) // 123

// ---------------- device scratch ----------------
__device__ float g_x[NN * DD];
__device__ float g_y[NN * DD];
__device__ float g_S[(size_t)NN * RR * DD];   // Z buffer [N,640] fp32
__device__ int   g_bcnt[NBKT];
__device__ float g_inv[NBKT];
__device__ int   g_rp[NBKT + 1];
__device__ int   g_wpos[NBKT];
__device__ int   g_aux[256];
__device__ int   g_eidx[EE];

// encoder B (round-3 layout [n][K] bf16 hi/lo)
#define OFF_DES 0
#define OFF_TW  (32 * 768)
__device__ __nv_bfloat16 g_Bh[2 * 32 * 768];
__device__ __nv_bfloat16 g_Bl[2 * 32 * 768];
// fragment-ordered B for k_wide: layer(6*8192) + W_in(8192) + W_o1(8192) words
#define FOFF_LAYER 0
#define FOFF_IN    49152
#define FOFF_O1    57344
__device__ uint32_t g_Bfh[65536];
__device__ uint32_t g_Bfl[65536];

__device__ __forceinline__ float lrelu(float v) { return v > 0.f ? v : 0.01f * v; }

__device__ __forceinline__ void mma16816(float* d, const uint32_t* a, const uint32_t* b) {
    asm volatile(
        "mma.sync.aligned.m16n8k16.row.col.f32.bf16.bf16.f32 "
        "{%0,%1,%2,%3}, {%4,%5,%6,%7}, {%8,%9}, {%0,%1,%2,%3};"
        : "+f"(d[0]), "+f"(d[1]), "+f"(d[2]), "+f"(d[3])
        : "r"(a[0]), "r"(a[1]), "r"(a[2]), "r"(a[3]), "r"(b[0]), "r"(b[1]));
}
__device__ __forceinline__ uint32_t smem_u32(const void* p) {
    uint32_t a;
    asm("{ .reg .u64 t; cvta.to.shared.u64 t, %1; cvt.u32.u64 %0, t; }" : "=r"(a) : "l"(p));
    return a;
}
__device__ __forceinline__ void cp16(uint32_t saddr, const void* g) {
    asm volatile("cp.async.cg.shared.global [%0], [%1], 16;" :: "r"(saddr), "l"(g));
}

// ---------------- small kernels ----------------
__global__ void k_zero_int(int* __restrict__ p, int n) {
    int i = blockIdx.x * blockDim.x + threadIdx.x;
    if (i < n) p[i] = 0;
}
__global__ void k_count(const int* __restrict__ ei, const int* __restrict__ et) {
    int e = blockIdx.x * blockDim.x + threadIdx.x;
    if (e < EE) atomicAdd(&g_bcnt[ei[EE + e] * RR + et[e]], 1);
}
__global__ void k_invert() {
    int i = blockIdx.x * blockDim.x + threadIdx.x;
    if (i < NBKT) g_inv[i] = 1.f / (float)max(g_bcnt[i], 1);
}
__global__ void k_scan1() {
    __shared__ int sh[SCAN_T];
    int b = blockIdx.x, t = threadIdx.x;
    int base = b * SCAN_BLOCK + t * SCAN_ELT;
    int v[SCAN_ELT], sum = 0;
#pragma unroll
    for (int i = 0; i < SCAN_ELT; i++) {
        v[i] = (base + i < NBKT) ? g_bcnt[base + i] : 0;
        sum += v[i];
    }
    sh[t] = sum;
    __syncthreads();
    for (int off = 1; off < SCAN_T; off <<= 1) {
        int x = (t >= off) ? sh[t - off] : 0;
        __syncthreads();
        sh[t] += x;
        __syncthreads();
    }
    int excl = sh[t] - sum;
#pragma unroll
    for (int i = 0; i < SCAN_ELT; i++) {
        if (base + i < NBKT) g_rp[base + i] = excl;
        excl += v[i];
    }
    if (t == SCAN_T - 1) g_aux[b] = sh[t];
}
__global__ void k_scan2() {
    __shared__ int sh[256];
    int t = threadIdx.x;
    int v = (t < NSCB) ? g_aux[t] : 0;
    sh[t] = v;
    __syncthreads();
    for (int off = 1; off < 256; off <<= 1) {
        int x = (t >= off) ? sh[t - off] : 0;
        __syncthreads();
        sh[t] += x;
        __syncthreads();
    }
    g_aux[t] = sh[t] - v;
}
__global__ void k_scan3() {
    int i = blockIdx.x * blockDim.x + threadIdx.x;
    if (i < NBKT) {
        int v = g_rp[i] + g_aux[i / SCAN_BLOCK];
        g_rp[i] = v;
        g_wpos[i] = v;
    }
    if (i == 0) g_rp[NBKT] = EE;
}
__global__ void k_fill(const int* __restrict__ ei, const int* __restrict__ et) {
    int e = blockIdx.x * blockDim.x + threadIdx.x;
    if (e >= EE) return;
    int b = ei[EE + e] * RR + et[e];
    int pos = atomicAdd(&g_wpos[b], 1);
    g_eidx[pos] = ei[e];
}

// split+transpose B for encoders: src [K][Nc] -> [Nc][K] hi/lo bf16
__global__ void k_prep(const float* __restrict__ B0, int K, int Nc,
                       __nv_bfloat16* __restrict__ Bh, __nv_bfloat16* __restrict__ Bl) {
    int i = blockIdx.x * blockDim.x + threadIdx.x;
    if (i >= Nc * K) return;
    int n = i / K, k = i % K;
    float v = B0[(size_t)k * Nc + n];
    __nv_bfloat16 h = __float2bfloat16_rn(v);
    Bh[(size_t)n * K + k] = h;
    Bl[(size_t)n * K + k] = __float2bfloat16_rn(v - __bfloat162float(h));
}
// fragment-ordered prep for k_wide (K=128). has_b1: layer mode (rel_w + root_w)
__global__ void k_prep_frag(const float* __restrict__ B0, const float* __restrict__ B1,
                            int ncb, int has_b1, uint32_t* __restrict__ oh, uint32_t* __restrict__ ol) {
    int i = blockIdx.x * blockDim.x + threadIdx.x;
    if (i >= ncb * 8192) return;
    int cb = i >> 13, rem = i & 8191;
    int r = rem & 1, lane = (rem >> 1) & 31, ks = (rem >> 6) & 7, nb = rem >> 9;
    int g = lane >> 2, t = lane & 3;
    int n = cb * 128 + nb * 8 + g;
    int k = ks * 16 + r * 8 + t * 2;
    float v0, v1;
    if (has_b1) {
        if (n < 640) {
            int rr = n >> 7, dout = n & 127;
            v0 = B0[rr * 16384 + k * 128 + dout];
            v1 = B0[rr * 16384 + (k + 1) * 128 + dout];
        } else {
            int dout = n - 640;
            v0 = B1[k * 128 + dout];
            v1 = B1[(k + 1) * 128 + dout];
        }
    } else {
        v0 = B0[k * 128 + n];
        v1 = B0[(k + 1) * 128 + n];
    }
    __nv_bfloat16 h0 = __float2bfloat16_rn(v0), h1 = __float2bfloat16_rn(v1);
    __nv_bfloat162 H(h0, h1);
    __nv_bfloat162 L = __floats2bfloat162_rn(v0 - __bfloat162float(h0), v1 - __bfloat162float(h1));
    oh[i] = *reinterpret_cast<uint32_t*>(&H);
    ol[i] = *reinterpret_cast<uint32_t*>(&L);
}

__global__ void k_enc_small(const float* __restrict__ np_, const float* __restrict__ cp,
                            const float* __restrict__ Wnp, const float* __restrict__ bnp,
                            const float* __restrict__ Wcp, const float* __restrict__ bcp,
                            float* __restrict__ q) {
    int i = blockIdx.x * blockDim.x + threadIdx.x;
    if (i >= NN * 64) return;
    int n = i >> 6, c = i & 63;
    float s; int col;
    if (c < 32) {
        s = bnp[c];
#pragma unroll
        for (int k = 0; k < 6; k++) s += np_[n * 6 + k] * Wnp[k * 32 + c];
        col = 64 + c;
    } else {
        int cc = c - 32;
        s = bcp[cc];
#pragma unroll
        for (int k = 0; k < 11; k++) s += cp[n * 11 + k] * Wcp[k * 32 + cc];
        col = 96 + cc;
    }
    q[n * DD + col] = lrelu(s);
}

__global__ void k_head(const float* __restrict__ z, const float* __restrict__ W,
                       const float* __restrict__ b, float* __restrict__ out) {
    int gt = blockIdx.x * blockDim.x + threadIdx.x;
    int warp = gt >> 5, lane = gt & 31;
    if (warp >= NN) return;
    float4 v = *reinterpret_cast<const float4*>(&z[(size_t)warp * DD + lane * 4]);
    float arr[4] = {v.x, v.y, v.z, v.w};
    float s0 = 0.f, s1 = 0.f;
#pragma unroll
    for (int t = 0; t < 4; t++) {
        s0 += arr[t] * W[(lane * 4 + t) * 2 + 0];
        s1 += arr[t] * W[(lane * 4 + t) * 2 + 1];
    }
#pragma unroll
    for (int o = 16; o > 0; o >>= 1) {
        s0 += __shfl_xor_sync(0xffffffffu, s0, o);
        s1 += __shfl_xor_sync(0xffffffffu, s1, o);
    }
    if (lane == 0) { out[warp * 2 + 0] = s0 + b[0]; out[warp * 2 + 1] = s1 + b[1]; }
}

// CSR gather aggregation: out[dst] += sum_r inv[dst,r] * sum_{src in bucket} Z[src, r*128:+128]
__global__ void k_agg(const float* __restrict__ Z, float* __restrict__ out) {
    int w = (blockIdx.x * blockDim.x + threadIdx.x) >> 5;
    int lane = threadIdx.x & 31;
    if (w >= NN) return;
    float4 acc = *reinterpret_cast<const float4*>(&out[(size_t)w * DD + lane * 4]);
#pragma unroll 1
    for (int g = 0; g < RR; g++) {
        int s = g_rp[w * RR + g], e = g_rp[w * RR + g + 1];
        if (s == e) continue;
        float sc = g_inv[w * RR + g];
        const float* Zg = Z + (size_t)g * 128 + lane * 4;
        float4 p0 = make_float4(0.f, 0.f, 0.f, 0.f);
        float4 p1 = make_float4(0.f, 0.f, 0.f, 0.f);
        int j = s;
        for (; j + 2 <= e; j += 2) {
            int s0 = g_eidx[j], s1 = g_eidx[j + 1];
            float4 v0 = *reinterpret_cast<const float4*>(Zg + (size_t)s0 * 640);
            float4 v1 = *reinterpret_cast<const float4*>(Zg + (size_t)s1 * 640);
            p0.x += v0.x; p0.y += v0.y; p0.z += v0.z; p0.w += v0.w;
            p1.x += v1.x; p1.y += v1.y; p1.z += v1.z; p1.w += v1.w;
        }
        if (j < e) {
            float4 v = *reinterpret_cast<const float4*>(Zg + (size_t)g_eidx[j] * 640);
            p0.x += v.x; p0.y += v.y; p0.z += v.z; p0.w += v.w;
        }
        acc.x += (p0.x + p1.x) * sc;
        acc.y += (p0.y + p1.y) * sc;
        acc.z += (p0.z + p1.z) * sc;
        acc.w += (p0.w + p1.w) * sc;
    }
    *reinterpret_cast<float4*>(&out[(size_t)w * DD + lane * 4]) = acc;
}

// ---------------- wide K=128 GEMM: A resident, B double-buffered cp.async ----------------
// ROUTE: cb<5 -> Z[row*640 + cb*128 + col]; cb==5 -> Cout[row*128+col]+bias. else: C=Cout, +bias, opt ACT.
template <int NCB, bool ROUTE, bool ACT>
__global__ __launch_bounds__(256)
void k_wide(const float* __restrict__ A,
            const uint32_t* __restrict__ gBh, const uint32_t* __restrict__ gBl,
            const float* __restrict__ bias, float* __restrict__ Z, float* __restrict__ Cout) {
    extern __shared__ uint32_t sm[];  // Ah[0,8192) Al[8192,16384) Bstage s at 16384+s*16384 (h then l 8192)
    const int tid = threadIdx.x, lane = tid & 31, wid = tid >> 5;
    const int wm = wid >> 2, wn = wid & 3;
    const int n0 = blockIdx.x * 128;
    const uint32_t smb = smem_u32(sm);

    // load + split-convert A (once)
#pragma unroll
    for (int it = 0; it < 16; it++) {
        int idx = it * 256 + tid;
        int row = idx >> 5, c4 = (idx & 31) * 4;
        int grow = n0 + row;
        float4 v = make_float4(0.f, 0.f, 0.f, 0.f);
        if (grow < NN) v = *reinterpret_cast<const float4*>(&A[(size_t)grow * DD + c4]);
        __nv_bfloat16 h0 = __float2bfloat16_rn(v.x), h1 = __float2bfloat16_rn(v.y);
        __nv_bfloat16 h2 = __float2bfloat16_rn(v.z), h3 = __float2bfloat16_rn(v.w);
        __nv_bfloat162 H01(h0, h1), H23(h2, h3);
        __nv_bfloat162 L01 = __floats2bfloat162_rn(v.x - __bfloat162float(h0), v.y - __bfloat162float(h1));
        __nv_bfloat162 L23 = __floats2bfloat162_rn(v.z - __bfloat162float(h2), v.w - __bfloat162float(h3));
        int mb = row >> 4, rm = row & 15, g = rm & 7, r1 = rm >> 3;
        int ks = c4 >> 4, khalf = (c4 >> 3) & 1, t0 = (c4 >> 1) & 3;
        int base = ((mb * 8 + ks) * 32 + g * 4 + t0) * 4 + (r1 + 2 * khalf);
        sm[base] = *reinterpret_cast<uint32_t*>(&H01);
        sm[base + 4] = *reinterpret_cast<uint32_t*>(&H23);
        sm[8192 + base] = *reinterpret_cast<uint32_t*>(&L01);
        sm[8192 + base + 4] = *reinterpret_cast<uint32_t*>(&L23);
    }

#define PREFETCH_B(CB, ST) do { \
    uint32_t so = smb + (16384u + (uint32_t)(ST) * 16384u) * 4u; \
    const uint32_t* gh_ = gBh + (size_t)(CB) * 8192; \
    const uint32_t* gl_ = gBl + (size_t)(CB) * 8192; \
    _Pragma("unroll") \
    for (int it_ = 0; it_ < 8; it_++) { \
        int w4 = (it_ * 256 + tid) * 4; \
        cp16(so + (uint32_t)w4 * 4u, gh_ + w4); \
        cp16(so + 32768u + (uint32_t)w4 * 4u, gl_ + w4); \
    } \
} while (0)

    PREFETCH_B(0, 0);
    asm volatile("cp.async.commit_group;" ::: "memory");

    float acc[4][4][4];
#pragma unroll 1
    for (int cb = 0; cb < NCB; cb++) {
        const int s = cb & 1;
        asm volatile("cp.async.wait_group 0;" ::: "memory");
        __syncthreads();
        if (cb + 1 < NCB) {
            PREFETCH_B(cb + 1, s ^ 1);
            asm volatile("cp.async.commit_group;" ::: "memory");
        }
#pragma unroll
        for (int mb = 0; mb < 4; mb++)
#pragma unroll
            for (int nb = 0; nb < 4; nb++)
#pragma unroll
                for (int q = 0; q < 4; q++) acc[mb][nb][q] = 0.f;

        const int bo = 16384 + s * 16384;
#pragma unroll
        for (int ks = 0; ks < 8; ks++) {
            uint32_t bh[4][2], bl[4][2];
#pragma unroll
            for (int nb = 0; nb < 4; nb++) {
                int nbg = wn * 4 + nb;
                uint2 h = *reinterpret_cast<uint2*>(&sm[bo + ((nbg * 8 + ks) * 32 + lane) * 2]);
                uint2 l = *reinterpret_cast<uint2*>(&sm[bo + 8192 + ((nbg * 8 + ks) * 32 + lane) * 2]);
                bh[nb][0] = h.x; bh[nb][1] = h.y; bl[nb][0] = l.x; bl[nb][1] = l.y;
            }
#pragma unroll
            for (int mb = 0; mb < 4; mb++) {
                int mbg = wm * 4 + mb;
                uint4 a4 = *reinterpret_cast<uint4*>(&sm[((mbg * 8 + ks) * 32 + lane) * 4]);
                uint4 b4 = *reinterpret_cast<uint4*>(&sm[8192 + ((mbg * 8 + ks) * 32 + lane) * 4]);
                uint32_t ah[4] = {a4.x, a4.y, a4.z, a4.w};
                uint32_t al[4] = {b4.x, b4.y, b4.z, b4.w};
#pragma unroll
                for (int nb = 0; nb < 4; nb++) {
                    mma16816(acc[mb][nb], ah, bh[nb]);
                    mma16816(acc[mb][nb], ah, bl[nb]);
                    mma16816(acc[mb][nb], al, bh[nb]);
                }
            }
        }
        // epilogue for this col-block
        int g = lane >> 2, t = lane & 3;
#pragma unroll
        for (int mb = 0; mb < 4; mb++) {
#pragma unroll
            for (int nb = 0; nb < 4; nb++) {
                int col = (wn * 4 + nb) * 8 + 2 * t;
                int row0 = n0 + wm * 64 + mb * 16 + g;
                float c0 = acc[mb][nb][0], c1 = acc[mb][nb][1];
                float c2 = acc[mb][nb][2], c3 = acc[mb][nb][3];
                if (ROUTE && cb < 5) {
                    if (row0 < NN) *reinterpret_cast<float2*>(&Z[(size_t)row0 * 640 + cb * 128 + col]) = make_float2(c0, c1);
                    if (row0 + 8 < NN) *reinterpret_cast<float2*>(&Z[(size_t)(row0 + 8) * 640 + cb * 128 + col]) = make_float2(c2, c3);
                } else {
                    float b0 = bias[col], b1 = bias[col + 1];
                    c0 += b0; c1 += b1; c2 += b0; c3 += b1;
                    if (ACT) { c0 = lrelu(c0); c1 = lrelu(c1); c2 = lrelu(c2); c3 = lrelu(c3); }
                    if (row0 < NN) *reinterpret_cast<float2*>(&Cout[(size_t)row0 * DD + col]) = make_float2(c0, c1);
                    if (row0 + 8 < NN) *reinterpret_cast<float2*>(&Cout[(size_t)(row0 + 8) * DD + col]) = make_float2(c2, c3);
                }
            }
        }
        __syncthreads();
    }
#undef PREFETCH_B
}

// ---------------- round-3 mma GEMM for encoders (BN=32, K=768) ----------------
template <int BN, bool ACT>
__global__ __launch_bounds__(256, 1)
void k_mma(const float* __restrict__ A0, int lda0, int K0,
           const __nv_bfloat16* __restrict__ Bh, const __nv_bfloat16* __restrict__ Bl,
           int K, const float* __restrict__ bias, float* __restrict__ C, int ldc) {
    constexpr int A_WORDS = 2048;
    constexpr int B_WORDS = (BN / 8) * 2 * 32 * 2;
    constexpr int MBW = (BN == 128) ? 4 : 1;
    constexpr int NBC = (BN == 128) ? 4 : 1;
    extern __shared__ uint32_t sm[];
    const int tid = threadIdx.x, lane = tid & 31, wid = tid >> 5;
    const int wm = (BN == 128) ? (wid >> 2) : wid;
    const int wn = (BN == 128) ? (wid & 3) : 0;
    const int n0 = blockIdx.x * 128;
    const int NC = K / 32;
    float acc[MBW][4][4];
#pragma unroll
    for (int i = 0; i < MBW; i++)
#pragma unroll
        for (int j = 0; j < 4; j++)
#pragma unroll
            for (int q = 0; q < 4; q++) acc[i][j][q] = 0.f;
    float4 av[4];
    uint4 bv[NBC];
#define GLOAD(I) do { \
    int k0 = (I) * 32; \
    _Pragma("unroll") \
    for (int it = 0; it < 4; it++) { \
        int idx = it * 256 + tid; int row = idx >> 3, c4 = (idx & 7) * 4; int grow = n0 + row; \
        av[it] = make_float4(0.f, 0.f, 0.f, 0.f); \
        if (grow < NN) av[it] = *reinterpret_cast<const float4*>(&A0[(size_t)grow * lda0 + k0 + c4]); \
    } \
    _Pragma("unroll") \
    for (int it = 0; it < NBC; it++) { \
        int idx = it * 256 + tid; int m = idx >= BN * 4; int idx2 = m ? idx - BN * 4 : idx; \
        int n = idx2 & (BN - 1); int kc = idx2 / BN; \
        const __nv_bfloat16* src = (m ? Bl : Bh) + (size_t)n * K + k0 + kc * 8; \
        bv[it] = *reinterpret_cast<const uint4*>(src); \
    } \
} while (0)
#define SSTORE(I) do { \
    int s_ = (I) & 1; \
    _Pragma("unroll") \
    for (int it = 0; it < 4; it++) { \
        int idx = it * 256 + tid; int row = idx >> 3, c4 = (idx & 7) * 4; \
        int mb = row >> 4, rm = row & 15, g = rm & 7, r1 = rm >> 3; \
        int ks = c4 >> 4, khalf = ((c4 & 15) >= 8) ? 1 : 0, r = r1 + 2 * khalf, t0 = (c4 >> 1) & 3; \
        float4 v = av[it]; \
        __nv_bfloat16 h0 = __float2bfloat16_rn(v.x), h1 = __float2bfloat16_rn(v.y); \
        __nv_bfloat16 h2 = __float2bfloat16_rn(v.z), h3 = __float2bfloat16_rn(v.w); \
        __nv_bfloat162 H01(h0, h1), H23(h2, h3); \
        __nv_bfloat162 L01 = __floats2bfloat162_rn(v.x - __bfloat162float(h0), v.y - __bfloat162float(h1)); \
        __nv_bfloat162 L23 = __floats2bfloat162_rn(v.z - __bfloat162float(h2), v.w - __bfloat162float(h3)); \
        int base = ((mb * 2 + ks) * 32) * 4 + r; \
        int ab0 = (s_ * 2 + 0) * A_WORDS + base, ab1 = (s_ * 2 + 1) * A_WORDS + base; \
        sm[ab0 + (g * 4 + t0) * 4]     = *reinterpret_cast<uint32_t*>(&H01); \
        sm[ab0 + (g * 4 + t0 + 1) * 4] = *reinterpret_cast<uint32_t*>(&H23); \
        sm[ab1 + (g * 4 + t0) * 4]     = *reinterpret_cast<uint32_t*>(&L01); \
        sm[ab1 + (g * 4 + t0 + 1) * 4] = *reinterpret_cast<uint32_t*>(&L23); \
    } \
    _Pragma("unroll") \
    for (int it = 0; it < NBC; it++) { \
        int idx = it * 256 + tid; int m = idx >= BN * 4; int idx2 = m ? idx - BN * 4 : idx; \
        int n = idx2 & (BN - 1); int kc = idx2 / BN; \
        int ks = kc >> 1, r = kc & 1, nb = n >> 3, g = n & 7; \
        int a0 = 8192 + (s_ * 2 + m) * B_WORDS + ((nb * 2 + ks) * 32 + g * 4) * 2 + r; \
        sm[a0 + 0] = bv[it].x; sm[a0 + 2] = bv[it].y; sm[a0 + 4] = bv[it].z; sm[a0 + 6] = bv[it].w; \
    } \
} while (0)
#define COMPUTE(I) do { \
    int s_ = (I) & 1; \
    _Pragma("unroll") \
    for (int ks = 0; ks < 2; ks++) { \
        uint32_t bhF[4][2], blF[4][2]; \
        _Pragma("unroll") \
        for (int nb = 0; nb < 4; nb++) { \
            int nb_g = wn * 4 + nb; \
            if (nb_g < BN / 8) { \
                uint2 h = *reinterpret_cast<uint2*>(&sm[8192 + (s_ * 2 + 0) * B_WORDS + ((nb_g * 2 + ks) * 32 + lane) * 2]); \
                uint2 l = *reinterpret_cast<uint2*>(&sm[8192 + (s_ * 2 + 1) * B_WORDS + ((nb_g * 2 + ks) * 32 + lane) * 2]); \
                bhF[nb][0] = h.x; bhF[nb][1] = h.y; blF[nb][0] = l.x; blF[nb][1] = l.y; \
            } \
        } \
        _Pragma("unroll") \
        for (int mb = 0; mb < MBW; mb++) { \
            int mb_g = wm * MBW + mb; \
            uint4 ah4 = *reinterpret_cast<uint4*>(&sm[(s_ * 2 + 0) * A_WORDS + ((mb_g * 2 + ks) * 32 + lane) * 4]); \
            uint4 al4 = *reinterpret_cast<uint4*>(&sm[(s_ * 2 + 1) * A_WORDS + ((mb_g * 2 + ks) * 32 + lane) * 4]); \
            uint32_t ah[4] = {ah4.x, ah4.y, ah4.z, ah4.w}; \
            uint32_t al[4] = {al4.x, al4.y, al4.z, al4.w}; \
            _Pragma("unroll") \
            for (int nb = 0; nb < 4; nb++) { \
                if (wn * 4 + nb < BN / 8) { \
                    mma16816(acc[mb][nb], ah, bhF[nb]); \
                    mma16816(acc[mb][nb], ah, blF[nb]); \
                    mma16816(acc[mb][nb], al, bhF[nb]); \
                } \
            } \
        } \
    } \
} while (0)
    GLOAD(0);
    SSTORE(0);
    __syncthreads();
    for (int i = 0; i < NC; i++) {
        if (i + 1 < NC) GLOAD(i + 1);
        COMPUTE(i);
        if (i + 1 < NC) SSTORE(i + 1);
        __syncthreads();
    }
    int g = lane >> 2, t = lane & 3;
#pragma unroll
    for (int mb = 0; mb < MBW; mb++) {
#pragma unroll
        for (int nb = 0; nb < 4; nb++) {
            if (wn * 4 + nb >= BN / 8) continue;
            int col = (wn * 4 + nb) * 8 + 2 * t;
            float b0 = bias[col], b1 = bias[col + 1];
            int row0 = n0 + wm * (MBW * 16) + mb * 16 + g;
            float c0 = acc[mb][nb][0] + b0, c1 = acc[mb][nb][1] + b1;
            float c2 = acc[mb][nb][2] + b0, c3 = acc[mb][nb][3] + b1;
            if (ACT) { c0 = lrelu(c0); c1 = lrelu(c1); c2 = lrelu(c2); c3 = lrelu(c3); }
            if (row0 < NN) *reinterpret_cast<float2*>(&C[(size_t)row0 * ldc + col]) = make_float2(c0, c1);
            if (row0 + 8 < NN) *reinterpret_cast<float2*>(&C[(size_t)(row0 + 8) * ldc + col]) = make_float2(c2, c3);
        }
    }
#undef GLOAD
#undef SSTORE
#undef COMPUTE
}

// ---------------- host launch ----------------
extern "C" void kernel_launch(void* const* d_in, const int* in_sizes, int n_in,
                              void* d_out, int out_size) {
    const float* des = (const float*)d_in[0];
    const float* tweet = (const float*)d_in[1];
    const float* np_ = (const float*)d_in[2];
    const float* cp = (const float*)d_in[3];
    const int* ei = (const int*)d_in[4];
    const int* et = (const int*)d_in[5];
    const float* W_des = (const float*)d_in[6];
    const float* b_des = (const float*)d_in[7];
    const float* W_tw = (const float*)d_in[8];
    const float* b_tw = (const float*)d_in[9];
    const float* W_np = (const float*)d_in[10];
    const float* b_np = (const float*)d_in[11];
    const float* W_cp = (const float*)d_in[12];
    const float* b_cp = (const float*)d_in[13];
    const float* W_in = (const float*)d_in[14];
    const float* b_in = (const float*)d_in[15];
    const float* rel_w = (const float*)d_in[16];
    const float* root_w = (const float*)d_in[17];
    const float* rgcn_b = (const float*)d_in[18];
    const float* W_o1 = (const float*)d_in[19];
    const float* b_o1 = (const float*)d_in[20];
    const float* W_o2 = (const float*)d_in[21];
    const float* b_o2 = (const float*)d_in[22];
    float* out = (float*)d_out;

    void *vx, *vy, *vS, *vbh, *vbl, *vfh, *vfl, *vbc;
    cudaGetSymbolAddress(&vx, g_x);
    cudaGetSymbolAddress(&vy, g_y);
    cudaGetSymbolAddress(&vS, g_S);
    cudaGetSymbolAddress(&vbh, g_Bh);
    cudaGetSymbolAddress(&vbl, g_Bl);
    cudaGetSymbolAddress(&vfh, g_Bfh);
    cudaGetSymbolAddress(&vfl, g_Bfl);
    cudaGetSymbolAddress(&vbc, g_bcnt);
    float* px = (float*)vx;
    float* py = (float*)vy;
    float* pZ = (float*)vS;
    __nv_bfloat16* pBh = (__nv_bfloat16*)vbh;
    __nv_bfloat16* pBl = (__nv_bfloat16*)vbl;
    uint32_t* pFh = (uint32_t*)vfh;
    uint32_t* pFl = (uint32_t*)vfl;
    int* pbc = (int*)vbc;

    const int GB = (NN + 127) / 128;  // 391
    const int SMEM32 = (8192 + 4 * 512) * 4;
    const int SMEM_WIDE2 = (16384 + 2 * 16384) * 4;  // 196608
    const int SMEM_WIDE1 = (16384 + 1 * 16384) * 4;  // 131072
    cudaFuncSetAttribute(k_mma<32, true>, cudaFuncAttributeMaxDynamicSharedMemorySize, SMEM32);
    cudaFuncSetAttribute(k_wide<6, true, false>, cudaFuncAttributeMaxDynamicSharedMemorySize, SMEM_WIDE2);
    cudaFuncSetAttribute(k_wide<1, false, true>, cudaFuncAttributeMaxDynamicSharedMemorySize, SMEM_WIDE1);

    // 1-5: preps
    k_prep<<<(32 * 768 + 255) / 256, 256>>>(W_des, 768, 32, pBh + OFF_DES, pBl + OFF_DES);
    k_prep<<<(32 * 768 + 255) / 256, 256>>>(W_tw, 768, 32, pBh + OFF_TW, pBl + OFF_TW);
    k_prep_frag<<<192, 256>>>(rel_w, root_w, 6, 1, pFh + FOFF_LAYER, pFl + FOFF_LAYER);
    k_prep_frag<<<32, 256>>>(W_in, nullptr, 1, 0, pFh + FOFF_IN, pFl + FOFF_IN);
    k_prep_frag<<<32, 256>>>(W_o1, nullptr, 1, 0, pFh + FOFF_O1, pFl + FOFF_O1);
    // 6: encoder des (ncu capture target)
    k_mma<32, true><<<GB, 256, SMEM32>>>(des, 768, 768, pBh + OFF_DES, pBl + OFF_DES, 768, b_des, py + 0, DD);
    k_mma<32, true><<<GB, 256, SMEM32>>>(tweet, 768, 768, pBh + OFF_TW, pBl + OFF_TW, 768, b_tw, py + 32, DD);
    k_enc_small<<<(NN * 64 + 255) / 256, 256>>>(np_, cp, W_np, b_np, W_cp, b_cp, py);

    // CSR build
    k_zero_int<<<(NBKT + 255) / 256, 256>>>(pbc, NBKT);
    k_count<<<(EE + 255) / 256, 256>>>(ei, et);
    k_invert<<<(NBKT + 255) / 256, 256>>>();
    k_scan1<<<NSCB, SCAN_T>>>();
    k_scan2<<<1, 256>>>();
    k_scan3<<<(NBKT + 255) / 256, 256>>>();
    k_fill<<<(EE + 255) / 256, 256>>>(ei, et);

    // x = lrelu(y @ W_in + b_in)
    k_wide<1, false, true><<<GB, 256, SMEM_WIDE1>>>(py, pFh + FOFF_IN, pFl + FOFF_IN, b_in, nullptr, px);

    // 4 RGCN layers
    float* cur = px;
    float* nxt = py;
    for (int l = 0; l < 4; l++) {
        k_wide<6, true, false><<<GB, 256, SMEM_WIDE2>>>(cur, pFh + FOFF_LAYER, pFl + FOFF_LAYER, rgcn_b, pZ, nxt);
        k_agg<<<(NN * 32 + 255) / 256, 256>>>(pZ, nxt);
        float* t = cur; cur = nxt; nxt = t;
    }

    // head
    k_wide<1, false, true><<<GB, 256, SMEM_WIDE1>>>(cur, pFh + FOFF_O1, pFl + FOFF_O1, b_o1, nullptr, nxt);
    k_head<<<(NN * 32 + 255) / 256, 256>>>(nxt, W_o2, b_o2, out);
}